// round 14
// baseline (speedup 1.0000x reference)
#include <cuda_runtime.h>
#include <cstdint>

// out[b, 0:128]   = emb[idx[b], :]    (128 f32)
// out[b, 128:146] = genre[idx[b], :]  (18 f32)
// idx is int32 (JAX downcasts int64 without x64).
//
// R13 gather/staging structure (warp = 4 rows, MLP-first __ldg gathers,
// warp-private smem staging, no block barrier) but the drain is ONE
// cp.async.bulk (TMA) store of the warp's contiguous 2336 B region:
//   - full-line async-proxy writes: no partial sectors, no STG wavefronts
//     through L1, different L2 write-allocation than STG -> tests whether
//     the output stream can stop displacing the L2-resident tables
//   - 2336 B = 146*16, region 16B-aligned (out is 256B-aligned, 2336%16==0)
// Protocol: STS -> fence.proxy.async.shared::cta -> __syncwarp -> lane 0
// issues bulk store + commit_group + wait_group 0 (smem not reused, but
// wait guarantees completion before thread exit).

#define ROWS_PER_WARP 4
#define WARP_STAGE_FLOATS (ROWS_PER_WARP * 146)   // 584 floats = 2336 B
#define WARP_STAGE_BYTES  (WARP_STAGE_FLOATS * 4)

__global__ void __launch_bounds__(256)
item_gather_concat_kernel(const int*    __restrict__ idx,
                          const float4* __restrict__ emb,   // [N, 32] float4
                          const float2* __restrict__ gen,   // [N, 9]  float2
                          float*        __restrict__ out,   // [B*146] floats
                          int B)
{
    __shared__ __align__(16) float s[8 * WARP_STAGE_FLOATS];   // 18.7 KB

    const int lane  = threadIdx.x & 31;
    const int w     = threadIdx.x >> 5;
    const int gwarp = (int)((blockIdx.x * (unsigned)blockDim.x + threadIdx.x) >> 5);
    const int r0    = gwarp * ROWS_PER_WARP;

    float* sw = s + w * WARP_STAGE_FLOATS;

    if (r0 + ROWS_PER_WARP <= B) {
        int4 iv = __ldcs((const int4*)(idx + r0));   // read-once broadcast
        int items[4] = {iv.x, iv.y, iv.z, iv.w};

        // Issue all independent gathers first (MLP), then stage.
        float4 e[4];
        float2 g[4];
        #pragma unroll
        for (int j = 0; j < 4; j++)
            e[j] = __ldg(&emb[(size_t)items[j] * 32 + lane]);
        #pragma unroll
        for (int j = 0; j < 4; j++)
            if (lane < 9)
                g[j] = __ldg(&gen[(size_t)items[j] * 9 + lane]);

        #pragma unroll
        for (int j = 0; j < 4; j++) {
            float* srow = sw + j * 146;
            *(float2*)(srow + lane * 4)     = make_float2(e[j].x, e[j].y);
            *(float2*)(srow + lane * 4 + 2) = make_float2(e[j].z, e[j].w);
            if (lane < 9)
                *(float2*)(srow + 128 + lane * 2) = g[j];
        }

        // Make STS visible to the async proxy, then one lane issues the
        // bulk store of the warp's whole 2336 B region.
        asm volatile("fence.proxy.async.shared::cta;" ::: "memory");
        __syncwarp();
        if (lane == 0) {
            float* gdst = out + (size_t)gwarp * WARP_STAGE_FLOATS;
            unsigned ssrc = (unsigned)__cvta_generic_to_shared(sw);
            asm volatile(
                "cp.async.bulk.global.shared::cta.bulk_group [%0], [%1], %2;"
                :: "l"(gdst), "r"(ssrc), "r"(WARP_STAGE_BYTES) : "memory");
            asm volatile("cp.async.bulk.commit_group;" ::: "memory");
            asm volatile("cp.async.bulk.wait_group 0;" ::: "memory");
        }
    } else {
        // Tail fallback (unused for B = 1M): one row at a time.
        for (int r = r0; r < B && r < r0 + ROWS_PER_WARP; r++) {
            int item = idx[r];
            float4 e = __ldg(&emb[(size_t)item * 32 + lane]);
            float2* o = (float2*)(out + (size_t)r * 146);
            o[lane * 2 + 0] = make_float2(e.x, e.y);
            o[lane * 2 + 1] = make_float2(e.z, e.w);
            if (lane < 9)
                o[64 + lane] = __ldg(&gen[(size_t)item * 9 + lane]);
        }
    }
}

extern "C" void kernel_launch(void* const* d_in, const int* in_sizes, int n_in,
                              void* d_out, int out_size)
{
    const int*    idx = (const int*)   d_in[0];
    const float4* emb = (const float4*)d_in[1];
    const float2* gen = (const float2*)d_in[2];
    float*        out = (float*)d_out;

    int B = in_sizes[0];                                   // 1048576
    int rowsPerBlock = 8 * ROWS_PER_WARP;                  // 8 warps/block
    int blocks = (B + rowsPerBlock - 1) / rowsPerBlock;    // 32768

    item_gather_concat_kernel<<<blocks, 256>>>(idx, emb, gen, out, B);
}